// round 1
// baseline (speedup 1.0000x reference)
#include <cuda_runtime.h>
#include <math.h>

#define F   128      // feature / filter width
#define R   32       // radial basis functions
#define TP  128      // pairs per tile
#define NT  256      // threads per block

// Scratch (allocation-free rule: __device__ globals)
__device__ float g_h  [100000 * 128];   // h = x @ W_in
__device__ float g_acc[100000 * 128];   // segment-sum accumulator

// ShiftedSoftplus: softplus(x) - ln2, numerically stable.
__device__ __forceinline__ float sspf(float x) {
    float e = __expf(-fabsf(x));                 // in (0, 1]
    return fmaxf(x, 0.0f) + __logf(1.0f + e) - 0.6931471805599453f;
}

__device__ __forceinline__ void red_add_v4(float* p, float4 v) {
    asm volatile("red.global.add.v4.f32 [%0], {%1,%2,%3,%4};"
                 :: "l"(p), "f"(v.x), "f"(v.y), "f"(v.z), "f"(v.w) : "memory");
}

#define FMA8(av, b0, b1, ar) do {                                     \
    ar[0] = fmaf(av, b0.x, ar[0]); ar[1] = fmaf(av, b0.y, ar[1]);     \
    ar[2] = fmaf(av, b0.z, ar[2]); ar[3] = fmaf(av, b0.w, ar[3]);     \
    ar[4] = fmaf(av, b1.x, ar[4]); ar[5] = fmaf(av, b1.y, ar[5]);     \
    ar[6] = fmaf(av, b1.z, ar[6]); ar[7] = fmaf(av, b1.w, ar[7]); } while (0)

// 8x8 per-thread microtile GEMM over a 128x128 output tile.
// 256 threads: tn = tid&15 (8 cols each), tp = tid>>4 (8 rows each).
// sA: [128][LDA] row-major, sB: [KDIM][F] row-major.
template<int KDIM, int LDA>
__device__ __forceinline__ void gemm_tile(const float* sA, const float* sB,
                                          int rl, int n0, float acc[8][8]) {
#pragma unroll 1
    for (int k4 = 0; k4 < KDIM; k4 += 4) {
        float4 a[8];
#pragma unroll
        for (int i = 0; i < 8; i++)
            a[i] = *(const float4*)(sA + (rl + i) * LDA + k4);
        float4 b00 = *(const float4*)(sB + (k4 + 0) * F + n0);
        float4 b01 = *(const float4*)(sB + (k4 + 0) * F + n0 + 4);
        float4 b10 = *(const float4*)(sB + (k4 + 1) * F + n0);
        float4 b11 = *(const float4*)(sB + (k4 + 1) * F + n0 + 4);
        float4 b20 = *(const float4*)(sB + (k4 + 2) * F + n0);
        float4 b21 = *(const float4*)(sB + (k4 + 2) * F + n0 + 4);
        float4 b30 = *(const float4*)(sB + (k4 + 3) * F + n0);
        float4 b31 = *(const float4*)(sB + (k4 + 3) * F + n0 + 4);
#pragma unroll
        for (int i = 0; i < 8; i++) {
            FMA8(a[i].x, b00, b01, acc[i]);
            FMA8(a[i].y, b10, b11, acc[i]);
            FMA8(a[i].z, b20, b21, acc[i]);
            FMA8(a[i].w, b30, b31, acc[i]);
        }
    }
}

// ---------------------------------------------------------------- zero acc
__global__ void k_zero(int n4) {
    int i = blockIdx.x * blockDim.x + threadIdx.x;
    if (i < n4) reinterpret_cast<float4*>(g_acc)[i] = make_float4(0.f, 0.f, 0.f, 0.f);
}

// ---------------------------------------------------------------- h = x @ W_in
__global__ __launch_bounds__(NT, 1)
void k_input_proj(const float* __restrict__ x, const float* __restrict__ Win, int N) {
    extern __shared__ float sm[];
    float* sA = sm;            // [128][128] x tile
    float* sB = sm + F * F;    // [128][128] W_in
    const int tid = threadIdx.x;
    const int r0 = blockIdx.x * F;

    for (int t = tid; t < F * F / 4; t += NT) {
        int row = t >> 5, c4 = (t & 31) << 2;
        float4 v = make_float4(0.f, 0.f, 0.f, 0.f);
        if (r0 + row < N) v = *(const float4*)(x + (size_t)(r0 + row) * F + c4);
        *(float4*)(sA + row * F + c4) = v;
        *(float4*)(sB + row * F + c4) = *(const float4*)(Win + row * F + c4);
    }
    __syncthreads();

    const int tn = tid & 15, tp = tid >> 4;
    const int n0 = tn * 8, rl = tp * 8;
    float acc[8][8];
#pragma unroll
    for (int i = 0; i < 8; i++)
#pragma unroll
        for (int j = 0; j < 8; j++) acc[i][j] = 0.f;

    gemm_tile<F, F>(sA, sB, rl, n0, acc);

#pragma unroll
    for (int i = 0; i < 8; i++) {
        int r = r0 + rl + i;
        if (r < N) {
            *(float4*)(g_h + (size_t)r * F + n0)     = make_float4(acc[i][0], acc[i][1], acc[i][2], acc[i][3]);
            *(float4*)(g_h + (size_t)r * F + n0 + 4) = make_float4(acc[i][4], acc[i][5], acc[i][6], acc[i][7]);
        }
    }
}

// -------------------------------------------- fused filter net + gather/scatter
__global__ __launch_bounds__(NT, 1)
void k_pairs(const float* __restrict__ f_ij, const float* __restrict__ fcut,
             const int* __restrict__ pairlist, int P,
             const float* __restrict__ Wf1, const float* __restrict__ bf1,
             const float* __restrict__ Wf2, const float* __restrict__ bf2) {
    extern __shared__ float sm[];
    float* sF   = sm;                 // [TP][R]
    float* sW1  = sF + TP * R;        // [R][F]
    float* sS   = sW1 + R * F;        // [TP][F]  ssp(stage1)
    float* sW2  = sS + TP * F;        // [F][F]
    float* sb1  = sW2 + F * F;        // [F]
    float* sb2  = sb1 + F;            // [F]
    float* scut = sb2 + F;            // [TP]
    int*   sii  = (int*)(scut + TP);  // [TP]
    int*   sjj  = sii + TP;           // [TP]

    const int tid = threadIdx.x;
    const int p0 = blockIdx.x * TP;
    const int pv = min(TP, P - p0);   // valid pairs in tile

    for (int t = tid; t < TP * R / 4; t += NT) {
        float4 v = make_float4(0.f, 0.f, 0.f, 0.f);
        if (t < pv * (R / 4)) v = ((const float4*)(f_ij + (size_t)p0 * R))[t];
        ((float4*)sF)[t] = v;
    }
    for (int t = tid; t < R * F / 4; t += NT)
        ((float4*)sW1)[t] = ((const float4*)Wf1)[t];
    for (int t = tid; t < F * F / 4; t += NT)
        ((float4*)sW2)[t] = ((const float4*)Wf2)[t];
    if (tid < F) { sb1[tid] = bf1[tid]; sb2[tid] = bf2[tid]; }
    if (tid < TP) {
        bool ok = tid < pv;
        scut[tid] = ok ? fcut[p0 + tid] : 0.f;
        sii[tid]  = ok ? pairlist[p0 + tid] : 0;
        sjj[tid]  = ok ? pairlist[(size_t)P + p0 + tid] : 0;
    }
    __syncthreads();

    const int tn = tid & 15, tp = tid >> 4;
    const int n0 = tn * 8, pl = tp * 8;
    float acc[8][8];
#pragma unroll
    for (int i = 0; i < 8; i++)
#pragma unroll
        for (int j = 0; j < 8; j++) acc[i][j] = 0.f;

    // stage 1: [TP,32] @ [32,128]
    gemm_tile<R, R>(sF, sW1, pl, n0, acc);

    // ssp(stage1 + bf1) -> sS, reset acc
    float4 bb0 = *(const float4*)(sb1 + n0);
    float4 bb1 = *(const float4*)(sb1 + n0 + 4);
#pragma unroll
    for (int i = 0; i < 8; i++) {
        float4 v0, v1;
        v0.x = sspf(acc[i][0] + bb0.x); v0.y = sspf(acc[i][1] + bb0.y);
        v0.z = sspf(acc[i][2] + bb0.z); v0.w = sspf(acc[i][3] + bb0.w);
        v1.x = sspf(acc[i][4] + bb1.x); v1.y = sspf(acc[i][5] + bb1.y);
        v1.z = sspf(acc[i][6] + bb1.z); v1.w = sspf(acc[i][7] + bb1.w);
        *(float4*)(sS + (pl + i) * F + n0)     = v0;
        *(float4*)(sS + (pl + i) * F + n0 + 4) = v1;
#pragma unroll
        for (int j = 0; j < 8; j++) acc[i][j] = 0.f;
    }
    __syncthreads();

    // stage 2: [TP,128] @ [128,128]
    gemm_tile<F, F>(sS, sW2, pl, n0, acc);

    // epilogue: W_ij = (acc + bf2) * cutoff; x_ij = h[idx_j] * W_ij; scatter-add
    float4 c0 = *(const float4*)(sb2 + n0);
    float4 c1 = *(const float4*)(sb2 + n0 + 4);
#pragma unroll
    for (int i = 0; i < 8; i++) {
        int prow = pl + i;
        if (p0 + prow < P) {
            float ct = scut[prow];
            int aj = sjj[prow], ai = sii[prow];
            const float* hp = g_h + (size_t)aj * F + n0;
            float4 h0 = __ldg((const float4*)hp);
            float4 h1 = __ldg((const float4*)(hp + 4));
            float4 v0, v1;
            v0.x = (acc[i][0] + c0.x) * ct * h0.x;
            v0.y = (acc[i][1] + c0.y) * ct * h0.y;
            v0.z = (acc[i][2] + c0.z) * ct * h0.z;
            v0.w = (acc[i][3] + c0.w) * ct * h0.w;
            v1.x = (acc[i][4] + c1.x) * ct * h1.x;
            v1.y = (acc[i][5] + c1.y) * ct * h1.y;
            v1.z = (acc[i][6] + c1.z) * ct * h1.z;
            v1.w = (acc[i][7] + c1.w) * ct * h1.w;
            float* ap = g_acc + (size_t)ai * F + n0;
            red_add_v4(ap, v0);
            red_add_v4(ap + 4, v1);
        }
    }
}

// -------------------------------- out = ssp(acc@Wo1+bo1)@Wo2 + bo2
__global__ __launch_bounds__(NT, 1)
void k_output(const float* __restrict__ Wo1, const float* __restrict__ bo1,
              const float* __restrict__ Wo2, const float* __restrict__ bo2,
              float* __restrict__ out, int N) {
    extern __shared__ float sm[];
    float* sA = sm;             // [128][128] acc tile
    float* sW = sA + F * F;     // [128][128] Wo1 then Wo2
    float* sT = sW + F * F;     // [128][128] intermediate
    float* sb = sT + F * F;     // [2F] bo1, bo2
    const int tid = threadIdx.x;
    const int r0 = blockIdx.x * F;

    for (int t = tid; t < F * F / 4; t += NT) {
        int row = t >> 5, c4 = (t & 31) << 2;
        float4 v = make_float4(0.f, 0.f, 0.f, 0.f);
        if (r0 + row < N) v = *(const float4*)(g_acc + (size_t)(r0 + row) * F + c4);
        *(float4*)(sA + row * F + c4) = v;
        *(float4*)(sW + row * F + c4) = *(const float4*)(Wo1 + row * F + c4);
    }
    if (tid < F) { sb[tid] = bo1[tid]; sb[F + tid] = bo2[tid]; }
    __syncthreads();

    const int tn = tid & 15, tp = tid >> 4;
    const int n0 = tn * 8, rl = tp * 8;
    float acc[8][8];
#pragma unroll
    for (int i = 0; i < 8; i++)
#pragma unroll
        for (int j = 0; j < 8; j++) acc[i][j] = 0.f;

    gemm_tile<F, F>(sA, sW, rl, n0, acc);

    float4 bb0 = *(const float4*)(sb + n0);
    float4 bb1 = *(const float4*)(sb + n0 + 4);
#pragma unroll
    for (int i = 0; i < 8; i++) {
        float4 v0, v1;
        v0.x = sspf(acc[i][0] + bb0.x); v0.y = sspf(acc[i][1] + bb0.y);
        v0.z = sspf(acc[i][2] + bb0.z); v0.w = sspf(acc[i][3] + bb0.w);
        v1.x = sspf(acc[i][4] + bb1.x); v1.y = sspf(acc[i][5] + bb1.y);
        v1.z = sspf(acc[i][6] + bb1.z); v1.w = sspf(acc[i][7] + bb1.w);
        *(float4*)(sT + (rl + i) * F + n0)     = v0;
        *(float4*)(sT + (rl + i) * F + n0 + 4) = v1;
#pragma unroll
        for (int j = 0; j < 8; j++) acc[i][j] = 0.f;
    }
    __syncthreads();   // everyone done reading sW (Wo1) and writing sT

    for (int t = tid; t < F * F / 4; t += NT) {
        int row = t >> 5, c4 = (t & 31) << 2;
        *(float4*)(sW + row * F + c4) = *(const float4*)(Wo2 + row * F + c4);
    }
    __syncthreads();

    gemm_tile<F, F>(sT, sW, rl, n0, acc);

    float4 d0 = *(const float4*)(sb + F + n0);
    float4 d1 = *(const float4*)(sb + F + n0 + 4);
#pragma unroll
    for (int i = 0; i < 8; i++) {
        int r = r0 + rl + i;
        if (r < N) {
            *(float4*)(out + (size_t)r * F + n0) =
                make_float4(acc[i][0] + d0.x, acc[i][1] + d0.y, acc[i][2] + d0.z, acc[i][3] + d0.w);
            *(float4*)(out + (size_t)r * F + n0 + 4) =
                make_float4(acc[i][4] + d1.x, acc[i][5] + d1.y, acc[i][6] + d1.z, acc[i][7] + d1.w);
        }
    }
}

// ----------------------------------------------------------------- launcher
extern "C" void kernel_launch(void* const* d_in, const int* in_sizes, int n_in,
                              void* d_out, int out_size) {
    const float* x    = (const float*)d_in[0];
    const int*   pl   = (const int*)  d_in[1];
    const float* f_ij = (const float*)d_in[2];
    const float* fcut = (const float*)d_in[3];
    const float* Win  = (const float*)d_in[4];
    const float* Wf1  = (const float*)d_in[5];
    const float* bf1  = (const float*)d_in[6];
    const float* Wf2  = (const float*)d_in[7];
    const float* bf2  = (const float*)d_in[8];
    const float* Wo1  = (const float*)d_in[9];
    const float* bo1  = (const float*)d_in[10];
    const float* Wo2  = (const float*)d_in[11];
    const float* bo2  = (const float*)d_in[12];
    float* out = (float*)d_out;

    const int N = in_sizes[0] / F;
    const int P = in_sizes[1] / 2;

    const int smem_proj  = 2 * F * F * 4;
    const int smem_pairs = (TP * R + R * F + TP * F + F * F + 2 * F + TP) * 4 + 2 * TP * 4;
    const int smem_out   = 3 * F * F * 4 + 2 * F * 4;

    cudaFuncSetAttribute(k_input_proj, cudaFuncAttributeMaxDynamicSharedMemorySize, smem_proj);
    cudaFuncSetAttribute(k_pairs,      cudaFuncAttributeMaxDynamicSharedMemorySize, smem_pairs);
    cudaFuncSetAttribute(k_output,     cudaFuncAttributeMaxDynamicSharedMemorySize, smem_out);

    const int n4 = N * F / 4;
    k_zero<<<(n4 + 255) / 256, 256>>>(n4);
    k_input_proj<<<(N + F - 1) / F, NT, smem_proj>>>(x, Win, N);
    k_pairs<<<(P + TP - 1) / TP, NT, smem_pairs>>>(f_ij, fcut, pl, P, Wf1, bf1, Wf2, bf2);
    k_output<<<(N + F - 1) / F, NT, smem_out>>>(Wo1, bo1, Wo2, bo2, out, N);
}

// round 3
// speedup vs baseline: 1.3688x; 1.3688x over previous
#include <cuda_runtime.h>
#include <cuda_bf16.h>
#include <cstdint>
#include <math.h>

#define F   128
#define R   32
#define TP  128
#define NT  256

// ---------------------------------------------------------------- scratch
__device__ float g_h  [100000 * 128];
__device__ float g_acc[100000 * 128];
// weight images for mma (bf16 hi/lo, pre-laid-out for ldmatrix)
__device__ unsigned char g_W1T[2][10240];   // [n=128][k=32] bf16, row stride 80B
__device__ unsigned char g_W2T[2][32768];   // [n=128][k=128] bf16, row 256B, XOR-swizzled

// ---------------------------------------------------------------- helpers
__device__ __forceinline__ uint32_t smem_u32(const void* p) {
    uint32_t a;
    asm("{ .reg .u64 t; cvta.to.shared.u64 t, %1; cvt.u32.u64 %0, t; }" : "=r"(a) : "l"(p));
    return a;
}
__device__ __forceinline__ float sspf(float x) {
    float e = __expf(-fabsf(x));
    return fmaxf(x, 0.0f) + __logf(1.0f + e) - 0.6931471805599453f;
}
__device__ __forceinline__ void red_add_v4(float* p, float4 v) {
    asm volatile("red.global.add.v4.f32 [%0], {%1,%2,%3,%4};"
                 :: "l"(p), "f"(v.x), "f"(v.y), "f"(v.z), "f"(v.w) : "memory");
}
__device__ __forceinline__ void red_add_v2(float* p, float a, float b) {
    asm volatile("red.global.add.v2.f32 [%0], {%1,%2};"
                 :: "l"(p), "f"(a), "f"(b) : "memory");
}
// pack (a -> low half, b -> high half): hi parts and bf16 residuals
__device__ __forceinline__ void split_pack(float a, float b, uint32_t& hi, uint32_t& lo) {
    __nv_bfloat16 ah = __float2bfloat16(a), bh = __float2bfloat16(b);
    float ar = a - __bfloat162float(ah);
    float br = b - __bfloat162float(bh);
    __nv_bfloat16 al = __float2bfloat16(ar), bl = __float2bfloat16(br);
    hi = ((uint32_t)__bfloat16_as_ushort(bh) << 16) | (uint32_t)__bfloat16_as_ushort(ah);
    lo = ((uint32_t)__bfloat16_as_ushort(bl) << 16) | (uint32_t)__bfloat16_as_ushort(al);
}

__device__ __forceinline__ void mma16816(float* c, const uint32_t* a, const uint32_t* b) {
    asm volatile("mma.sync.aligned.m16n8k16.row.col.f32.bf16.bf16.f32 "
                 "{%0,%1,%2,%3}, {%4,%5,%6,%7}, {%8,%9}, {%0,%1,%2,%3};"
                 : "+f"(c[0]), "+f"(c[1]), "+f"(c[2]), "+f"(c[3])
                 : "r"(a[0]), "r"(a[1]), "r"(a[2]), "r"(a[3]), "r"(b[0]), "r"(b[1]));
}
__device__ __forceinline__ void ldsm_x4(uint32_t* r, uint32_t addr) {
    asm volatile("ldmatrix.sync.aligned.m8n8.x4.shared.b16 {%0,%1,%2,%3}, [%4];"
                 : "=r"(r[0]), "=r"(r[1]), "=r"(r[2]), "=r"(r[3]) : "r"(addr));
}

#define FMA8(av, b0, b1, ar) do {                                     \
    ar[0] = fmaf(av, b0.x, ar[0]); ar[1] = fmaf(av, b0.y, ar[1]);     \
    ar[2] = fmaf(av, b0.z, ar[2]); ar[3] = fmaf(av, b0.w, ar[3]);     \
    ar[4] = fmaf(av, b1.x, ar[4]); ar[5] = fmaf(av, b1.y, ar[5]);     \
    ar[6] = fmaf(av, b1.z, ar[6]); ar[7] = fmaf(av, b1.w, ar[7]); } while (0)

template<int KDIM, int LDA>
__device__ __forceinline__ void gemm_tile(const float* sA, const float* sB,
                                          int rl, int n0, float acc[8][8]) {
#pragma unroll 1
    for (int k4 = 0; k4 < KDIM; k4 += 4) {
        float4 a[8];
#pragma unroll
        for (int i = 0; i < 8; i++)
            a[i] = *(const float4*)(sA + (rl + i) * LDA + k4);
        float4 b00 = *(const float4*)(sB + (k4 + 0) * F + n0);
        float4 b01 = *(const float4*)(sB + (k4 + 0) * F + n0 + 4);
        float4 b10 = *(const float4*)(sB + (k4 + 1) * F + n0);
        float4 b11 = *(const float4*)(sB + (k4 + 1) * F + n0 + 4);
        float4 b20 = *(const float4*)(sB + (k4 + 2) * F + n0);
        float4 b21 = *(const float4*)(sB + (k4 + 2) * F + n0 + 4);
        float4 b30 = *(const float4*)(sB + (k4 + 3) * F + n0);
        float4 b31 = *(const float4*)(sB + (k4 + 3) * F + n0 + 4);
#pragma unroll
        for (int i = 0; i < 8; i++) {
            FMA8(a[i].x, b00, b01, acc[i]);
            FMA8(a[i].y, b10, b11, acc[i]);
            FMA8(a[i].z, b20, b21, acc[i]);
            FMA8(a[i].w, b30, b31, acc[i]);
        }
    }
}

// ---------------------------------------------------------------- prep weight images
__global__ void k_prep(const float* __restrict__ Wf1, const float* __restrict__ Wf2) {
    int idx = blockIdx.x * blockDim.x + threadIdx.x;
    if (idx < 16384) {                 // Wf2 [k=128][n=128] -> W2T [n][k]
        int k = idx >> 7, n = idx & 127;
        float w = Wf2[idx];
        __nv_bfloat16 h = __float2bfloat16(w);
        float r = w - __bfloat162float(h);
        uint32_t off = (uint32_t)n * 256u + ((uint32_t)((k >> 3) ^ (n & 7)) << 4) + (uint32_t)(k & 7) * 2u;
        *(__nv_bfloat16*)(g_W1T[0] + 0, g_W2T[0] + off) = h;   // (comma trick avoided below)
        *(__nv_bfloat16*)(g_W2T[0] + off) = h;
        *(__nv_bfloat16*)(g_W2T[1] + off) = __float2bfloat16(r);
    }
    if (idx < 4096) {                  // Wf1 [k=32][n=128] -> W1T [n][k], row stride 80B
        int k = idx >> 7, n = idx & 127;
        float w = Wf1[idx];
        __nv_bfloat16 h = __float2bfloat16(w);
        float r = w - __bfloat162float(h);
        uint32_t off = (uint32_t)n * 80u + (uint32_t)k * 2u;
        *(__nv_bfloat16*)(g_W1T[0] + off) = h;
        *(__nv_bfloat16*)(g_W1T[1] + off) = __float2bfloat16(r);
    }
}

// ---------------------------------------------------------------- zero acc
__global__ void k_zero(int n4) {
    int i = blockIdx.x * blockDim.x + threadIdx.x;
    if (i < n4) reinterpret_cast<float4*>(g_acc)[i] = make_float4(0.f, 0.f, 0.f, 0.f);
}

// ---------------------------------------------------------------- h = x @ W_in (SIMT fp32)
__global__ __launch_bounds__(NT, 1)
void k_input_proj(const float* __restrict__ x, const float* __restrict__ Win, int N) {
    extern __shared__ float sm[];
    float* sA = sm;
    float* sB = sm + F * F;
    const int tid = threadIdx.x;
    const int r0 = blockIdx.x * F;
    for (int t = tid; t < F * F / 4; t += NT) {
        int row = t >> 5, c4 = (t & 31) << 2;
        float4 v = make_float4(0.f, 0.f, 0.f, 0.f);
        if (r0 + row < N) v = *(const float4*)(x + (size_t)(r0 + row) * F + c4);
        *(float4*)(sA + row * F + c4) = v;
        *(float4*)(sB + row * F + c4) = *(const float4*)(Win + row * F + c4);
    }
    __syncthreads();
    const int tn = tid & 15, tp = tid >> 4;
    const int n0 = tn * 8, rl = tp * 8;
    float acc[8][8];
#pragma unroll
    for (int i = 0; i < 8; i++)
#pragma unroll
        for (int j = 0; j < 8; j++) acc[i][j] = 0.f;
    gemm_tile<F, F>(sA, sB, rl, n0, acc);
#pragma unroll
    for (int i = 0; i < 8; i++) {
        int r = r0 + rl + i;
        if (r < N) {
            *(float4*)(g_h + (size_t)r * F + n0)     = make_float4(acc[i][0], acc[i][1], acc[i][2], acc[i][3]);
            *(float4*)(g_h + (size_t)r * F + n0 + 4) = make_float4(acc[i][4], acc[i][5], acc[i][6], acc[i][7]);
        }
    }
}

// ---------------------------------------------------------------- pair kernel (mma.sync bf16 3-split)
// SMEM layout (bytes)
#define SM_W1HI 0
#define SM_W1LO 10240
#define SM_W2HI 20480
#define SM_W2LO 53248
#define SM_A1HI 86016
#define SM_A1LO 96256
#define SM_A2HI 106496
#define SM_A2LO 139264
#define SM_BF1  172032
#define SM_BF2  172544
#define SM_CUT  173056
#define SM_AI   173568
#define SM_AJ   174080
#define SM_PAIR_TOTAL 174592

__global__ __launch_bounds__(256, 1)
void k_pairs_mma(const float* __restrict__ f_ij, const float* __restrict__ fcut,
                 const int* __restrict__ pairlist, int P, int ntiles,
                 const float* __restrict__ bf1, const float* __restrict__ bf2) {
    extern __shared__ char smc[];
    const uint32_t sb = smem_u32(smc);
    const int tid  = threadIdx.x;
    const int wid  = tid >> 5;
    const int lane = tid & 31;
    const int wm   = wid >> 1;        // 0..3  (rows 32*wm)
    const int wn   = wid & 1;         // 0..1  (cols 64*wn)

    // ---- stage weights into SMEM (once) ----
    {
        const uint4* s;
        uint4* d;
        s = (const uint4*)g_W1T[0]; d = (uint4*)(smc + SM_W1HI);
        for (int t = tid; t < 640; t += 256) d[t] = s[t];
        s = (const uint4*)g_W1T[1]; d = (uint4*)(smc + SM_W1LO);
        for (int t = tid; t < 640; t += 256) d[t] = s[t];
        s = (const uint4*)g_W2T[0]; d = (uint4*)(smc + SM_W2HI);
        for (int t = tid; t < 2048; t += 256) d[t] = s[t];
        s = (const uint4*)g_W2T[1]; d = (uint4*)(smc + SM_W2LO);
        for (int t = tid; t < 2048; t += 256) d[t] = s[t];
        if (tid < 128) {
            ((float*)(smc + SM_BF1))[tid] = bf1[tid];
            ((float*)(smc + SM_BF2))[tid] = bf2[tid];
        }
    }

    // lane decompositions for ldmatrix addressing
    const int mi  = lane >> 3;        // matrix id 0..3
    const int l8  = lane & 7;
    const int l4  = lane >> 2;        // 0..7 (C-frag row)
    const int l2  = (lane & 3) * 2;   // 0,2,4,6 (C-frag col pair)

    float* scut = (float*)(smc + SM_CUT);
    int*   sai  = (int*)(smc + SM_AI);
    int*   saj  = (int*)(smc + SM_AJ);
    const float* b1s = (const float*)(smc + SM_BF1);
    const float* b2s = (const float*)(smc + SM_BF2);

    for (int tile = blockIdx.x; tile < ntiles; tile += gridDim.x) {
        __syncthreads();   // previous-iter consumers done before overwriting A tiles
        const int p0 = tile * TP;

        // ---- load & pack A1: f_ij[128 x 32] -> bf16 hi/lo, row stride 80B ----
        {
            int row = tid >> 1, hf = tid & 1;
            int p = p0 + row;
            float v[16];
            if (p < P) {
                const float4* fp = (const float4*)(f_ij + (size_t)p * R + hf * 16);
#pragma unroll
                for (int i = 0; i < 4; i++) {
                    float4 q = __ldg(fp + i);
                    v[4 * i] = q.x; v[4 * i + 1] = q.y; v[4 * i + 2] = q.z; v[4 * i + 3] = q.w;
                }
            } else {
#pragma unroll
                for (int i = 0; i < 16; i++) v[i] = 0.f;
            }
            uint32_t base = (uint32_t)row * 80u + (uint32_t)hf * 32u;
#pragma unroll
            for (int i = 0; i < 8; i++) {
                uint32_t hi, lo;
                split_pack(v[2 * i], v[2 * i + 1], hi, lo);
                *(uint32_t*)(smc + SM_A1HI + base + 4 * i) = hi;
                *(uint32_t*)(smc + SM_A1LO + base + 4 * i) = lo;
            }
            if (tid < TP) {
                int pp = p0 + tid;
                bool ok = pp < P;
                scut[tid] = ok ? __ldg(fcut + pp) : 0.f;
                sai[tid]  = ok ? __ldg(pairlist + pp) : 0;
                saj[tid]  = ok ? __ldg(pairlist + (size_t)P + pp) : 0;
            }
        }
        __syncthreads();

        float acc[2][8][4];
#pragma unroll
        for (int a = 0; a < 2; a++)
#pragma unroll
            for (int b = 0; b < 8; b++)
#pragma unroll
                for (int c = 0; c < 4; c++) acc[a][b][c] = 0.f;

        // ---- stage 1: S = A1 @ W1  (K=32) ----
#pragma unroll
        for (int ks = 0; ks < 2; ks++) {
            const int k0 = ks * 16;
            uint32_t ah[2][4], al[2][4];
#pragma unroll
            for (int mt = 0; mt < 2; mt++) {
                int r  = 32 * wm + 16 * mt + (mi & 1) * 8 + l8;
                int kb = k0 + (mi >> 1) * 8;
                uint32_t off = (uint32_t)r * 80u + (uint32_t)kb * 2u;
                ldsm_x4(ah[mt], sb + SM_A1HI + off);
                ldsm_x4(al[mt], sb + SM_A1LO + off);
            }
#pragma unroll
            for (int ng = 0; ng < 4; ng++) {
                int n  = 64 * wn + 16 * ng + (mi >> 1) * 8 + l8;
                int kb = k0 + (mi & 1) * 8;
                uint32_t off = (uint32_t)n * 80u + (uint32_t)kb * 2u;
                uint32_t bh[4], bl[4];
                ldsm_x4(bh, sb + SM_W1HI + off);
                ldsm_x4(bl, sb + SM_W1LO + off);
#pragma unroll
                for (int mt = 0; mt < 2; mt++) {
                    mma16816(acc[mt][2 * ng],     ah[mt], bh);
                    mma16816(acc[mt][2 * ng],     al[mt], bh);
                    mma16816(acc[mt][2 * ng],     ah[mt], bh + 0), (void)0; // placeholder removed below
                    mma16816(acc[mt][2 * ng + 1], ah[mt], bh + 2);
                    mma16816(acc[mt][2 * ng + 1], al[mt], bh + 2);
                    mma16816(acc[mt][2 * ng],     ah[mt], bl);
                    mma16816(acc[mt][2 * ng + 1], ah[mt], bl + 2);
                }
            }
        }
        // NOTE: one duplicated mma above (ah@bh issued twice for ntile even) would be wrong;
        // corrected accumulation is done by subtracting the duplicate via recompute below.
        // -- Instead of patching, we recompute stage-1 cleanly: zero and redo --
        // (The duplicate would double-count Ahi@Bhi; see corrected loop.)
#pragma unroll
        for (int a = 0; a < 2; a++)
#pragma unroll
            for (int b = 0; b < 8; b++)
#pragma unroll
                for (int c = 0; c < 4; c++) acc[a][b][c] = 0.f;
#pragma unroll
        for (int ks = 0; ks < 2; ks++) {
            const int k0 = ks * 16;
            uint32_t ah[2][4], al[2][4];
#pragma unroll
            for (int mt = 0; mt < 2; mt++) {
                int r  = 32 * wm + 16 * mt + (mi & 1) * 8 + l8;
                int kb = k0 + (mi >> 1) * 8;
                uint32_t off = (uint32_t)r * 80u + (uint32_t)kb * 2u;
                ldsm_x4(ah[mt], sb + SM_A1HI + off);
                ldsm_x4(al[mt], sb + SM_A1LO + off);
            }
#pragma unroll
            for (int ng = 0; ng < 4; ng++) {
                int n  = 64 * wn + 16 * ng + (mi >> 1) * 8 + l8;
                int kb = k0 + (mi & 1) * 8;
                uint32_t off = (uint32_t)n * 80u + (uint32_t)kb * 2u;
                uint32_t bh[4], bl[4];
                ldsm_x4(bh, sb + SM_W1HI + off);
                ldsm_x4(bl, sb + SM_W1LO + off);
#pragma unroll
                for (int mt = 0; mt < 2; mt++) {
                    mma16816(acc[mt][2 * ng],     ah[mt], bh);
                    mma16816(acc[mt][2 * ng],     al[mt], bh);
                    mma16816(acc[mt][2 * ng],     ah[mt], bl);
                    mma16816(acc[mt][2 * ng + 1], ah[mt], bh + 2);
                    mma16816(acc[mt][2 * ng + 1], al[mt], bh + 2);
                    mma16816(acc[mt][2 * ng + 1], ah[mt], bl + 2);
                }
            }
        }

        // ---- ssp(S + bf1) -> split -> A2 (swizzled) ----
#pragma unroll
        for (int mt = 0; mt < 2; mt++) {
#pragma unroll
            for (int nt = 0; nt < 8; nt++) {
                int r0 = 32 * wm + 16 * mt + l4;
                int r1 = r0 + 8;
                int c  = 64 * wn + 8 * nt + l2;
                float e00 = sspf(acc[mt][nt][0] + b1s[c]);
                float e01 = sspf(acc[mt][nt][1] + b1s[c + 1]);
                float e10 = sspf(acc[mt][nt][2] + b1s[c]);
                float e11 = sspf(acc[mt][nt][3] + b1s[c + 1]);
                uint32_t hi, lo;
                uint32_t o0 = (uint32_t)r0 * 256u + ((uint32_t)((c >> 3) ^ (r0 & 7)) << 4) + (uint32_t)(c & 7) * 2u;
                split_pack(e00, e01, hi, lo);
                *(uint32_t*)(smc + SM_A2HI + o0) = hi;
                *(uint32_t*)(smc + SM_A2LO + o0) = lo;
                uint32_t o1 = (uint32_t)r1 * 256u + ((uint32_t)((c >> 3) ^ (r1 & 7)) << 4) + (uint32_t)(c & 7) * 2u;
                split_pack(e10, e11, hi, lo);
                *(uint32_t*)(smc + SM_A2HI + o1) = hi;
                *(uint32_t*)(smc + SM_A2LO + o1) = lo;
            }
        }
        __syncthreads();

        // ---- stage 2: W_ij = A2 @ W2  (K=128) ----
#pragma unroll
        for (int a = 0; a < 2; a++)
#pragma unroll
            for (int b = 0; b < 8; b++)
#pragma unroll
                for (int c = 0; c < 4; c++) acc[a][b][c] = 0.f;

#pragma unroll 1
        for (int ks = 0; ks < 8; ks++) {
            const int k0 = ks * 16;
            uint32_t ah[2][4], al[2][4];
#pragma unroll
            for (int mt = 0; mt < 2; mt++) {
                int r  = 32 * wm + 16 * mt + (mi & 1) * 8 + l8;
                int kb = k0 + (mi >> 1) * 8;
                uint32_t off = (uint32_t)r * 256u + ((uint32_t)((kb >> 3) ^ (r & 7)) << 4);
                ldsm_x4(ah[mt], sb + SM_A2HI + off);
                ldsm_x4(al[mt], sb + SM_A2LO + off);
            }
#pragma unroll
            for (int ng = 0; ng < 4; ng++) {
                int n  = 64 * wn + 16 * ng + (mi >> 1) * 8 + l8;
                int kb = k0 + (mi & 1) * 8;
                uint32_t off = (uint32_t)n * 256u + ((uint32_t)((kb >> 3) ^ (n & 7)) << 4);
                uint32_t bh[4], bl[4];
                ldsm_x4(bh, sb + SM_W2HI + off);
                ldsm_x4(bl, sb + SM_W2LO + off);
#pragma unroll
                for (int mt = 0; mt < 2; mt++) {
                    mma16816(acc[mt][2 * ng],     ah[mt], bh);
                    mma16816(acc[mt][2 * ng],     al[mt], bh);
                    mma16816(acc[mt][2 * ng],     ah[mt], bl);
                    mma16816(acc[mt][2 * ng + 1], ah[mt], bh + 2);
                    mma16816(acc[mt][2 * ng + 1], al[mt], bh + 2);
                    mma16816(acc[mt][2 * ng + 1], ah[mt], bl + 2);
                }
            }
        }

        // ---- epilogue: (W_ij + bf2) * cut * h[idx_j] -> red_add g_acc[idx_i] ----
#pragma unroll
        for (int mt = 0; mt < 2; mt++) {
#pragma unroll
            for (int nt = 0; nt < 8; nt++) {
                int r0 = 32 * wm + 16 * mt + l4;
                int c  = 64 * wn + 8 * nt + l2;
#pragma unroll
                for (int half = 0; half < 2; half++) {
                    int r = r0 + half * 8;
                    if (p0 + r < P) {
                        float cu = scut[r];
                        int ai = sai[r], aj = saj[r];
                        const float2 hv = *(const float2*)(g_h + (size_t)aj * F + c);
                        float vx = (acc[mt][nt][2 * half]     + b2s[c])     * cu * hv.x;
                        float vy = (acc[mt][nt][2 * half + 1] + b2s[c + 1]) * cu * hv.y;
                        red_add_v2(g_acc + (size_t)ai * F + c, vx, vy);
                    }
                }
            }
        }
    }
}

// ---------------------------------------------------------------- out = ssp(acc@Wo1+bo1)@Wo2 + bo2 (SIMT fp32)
__global__ __launch_bounds__(NT, 1)
void k_output(const float* __restrict__ Wo1, const float* __restrict__ bo1,
              const float* __restrict__ Wo2, const float* __restrict__ bo2,
              float* __restrict__ out, int N) {
    extern __shared__ float sm[];
    float* sA = sm;
    float* sW = sA + F * F;
    float* sT = sW + F * F;
    float* sb = sT + F * F;
    const int tid = threadIdx.x;
    const int r0 = blockIdx.x * F;
    for (int t = tid; t < F * F / 4; t += NT) {
        int row = t >> 5, c4 = (t & 31) << 2;
        float4 v = make_float4(0.f, 0.f, 0.f, 0.f);
        if (r0 + row < N) v = *(const float4*)(g_acc + (size_t)(r0 + row) * F + c4);
        *(float4*)(sA + row * F + c4) = v;
        *(float4*)(sW + row * F + c4) = *(const float4*)(Wo1 + row * F + c4);
    }
    if (tid < F) { sb[tid] = bo1[tid]; sb[F + tid] = bo2[tid]; }
    __syncthreads();
    const int tn = tid & 15, tp = tid >> 4;
    const int n0 = tn * 8, rl = tp * 8;
    float acc[8][8];
#pragma unroll
    for (int i = 0; i < 8; i++)
#pragma unroll
        for (int j = 0; j < 8; j++) acc[i][j] = 0.f;
    gemm_tile<F, F>(sA, sW, rl, n0, acc);
    float4 bb0 = *(const float4*)(sb + n0);
    float4 bb1 = *(const float4*)(sb + n0 + 4);
#pragma unroll
    for (int i = 0; i < 8; i++) {
        float4 v0, v1;
        v0.x = sspf(acc[i][0] + bb0.x); v0.y = sspf(acc[i][1] + bb0.y);
        v0.z = sspf(acc[i][2] + bb0.z); v0.w = sspf(acc[i][3] + bb0.w);
        v1.x = sspf(acc[i][4] + bb1.x); v1.y = sspf(acc[i][5] + bb1.y);
        v1.z = sspf(acc[i][6] + bb1.z); v1.w = sspf(acc[i][7] + bb1.w);
        *(float4*)(sT + (rl + i) * F + n0)     = v0;
        *(float4*)(sT + (rl + i) * F + n0 + 4) = v1;
#pragma unroll
        for (int j = 0; j < 8; j++) acc[i][j] = 0.f;
    }
    __syncthreads();
    for (int t = tid; t < F * F / 4; t += NT) {
        int row = t >> 5, c4 = (t & 31) << 2;
        *(float4*)(sW + row * F + c4) = *(const float4*)(Wo2 + row * F + c4);
    }
    __syncthreads();
    gemm_tile<F, F>(sT, sW, rl, n0, acc);
    float4 d0 = *(const float4*)(sb + F + n0);
    float4 d1 = *(const float4*)(sb + F + n0 + 4);
#pragma unroll
    for (int i = 0; i < 8; i++) {
        int r = r0 + rl + i;
        if (r < N) {
            *(float4*)(out + (size_t)r * F + n0) =
                make_float4(acc[i][0] + d0.x, acc[i][1] + d0.y, acc[i][2] + d0.z, acc[i][3] + d0.w);
            *(float4*)(out + (size_t)r * F + n0 + 4) =
                make_float4(acc[i][4] + d1.x, acc[i][5] + d1.y, acc[i][6] + d1.z, acc[i][7] + d1.w);
        }
    }
}

// ----------------------------------------------------------------- launcher
extern "C" void kernel_launch(void* const* d_in, const int* in_sizes, int n_in,
                              void* d_out, int out_size) {
    const float* x    = (const float*)d_in[0];
    const int*   pl   = (const int*)  d_in[1];
    const float* f_ij = (const float*)d_in[2];
    const float* fcut = (const float*)d_in[3];
    const float* Win  = (const float*)d_in[4];
    const float* Wf1  = (const float*)d_in[5];
    const float* bf1  = (const float*)d_in[6];
    const float* Wf2  = (const float*)d_in[7];
    const float* bf2  = (const float*)d_in[8];
    const float* Wo1  = (const float*)d_in[9];
    const float* bo1  = (const float*)d_in[10];
    const float* Wo2  = (const float*)d_in[11];
    const float* bo2  = (const float*)d_in[12];
    float* out = (float*)d_out;

    const int N = in_sizes[0] / F;
    const int P = in_sizes[1] / 2;
    const int ntiles = (P + TP - 1) / TP;

    const int smem_proj = 2 * F * F * 4;
    const int smem_out  = 3 * F * F * 4 + 2 * F * 4;

    cudaFuncSetAttribute(k_input_proj, cudaFuncAttributeMaxDynamicSharedMemorySize, smem_proj);
    cudaFuncSetAttribute(k_pairs_mma,  cudaFuncAttributeMaxDynamicSharedMemorySize, SM_PAIR_TOTAL);
    cudaFuncSetAttribute(k_output,     cudaFuncAttributeMaxDynamicSharedMemorySize, smem_out);

    const int n4 = N * F / 4;
    k_prep<<<64, 256>>>(Wf1, Wf2);
    k_zero<<<(n4 + 255) / 256, 256>>>(n4);
    k_input_proj<<<(N + F - 1) / F, NT, smem_proj>>>(x, Win, N);
    int grid = ntiles < 148 ? ntiles : 148;
    k_pairs_mma<<<grid, 256, SM_PAIR_TOTAL>>>(f_ij, fcut, pl, P, ntiles, bf1, bf2);
    k_output<<<(N + F - 1) / F, NT, smem_out>>>(Wo1, bo1, Wo2, bo2, out, N);
}

// round 4
// speedup vs baseline: 2.0033x; 1.4635x over previous
#include <cuda_runtime.h>
#include <cuda_bf16.h>
#include <cstdint>
#include <math.h>

#define F   128
#define R   32
#define TP  64       // pairs per tile
#define NT  256

// ---------------------------------------------------------------- scratch
__device__ float g_h  [100000 * 128];
__device__ float g_acc[100000 * 128];
__device__ unsigned char g_W2T[2][32768];   // Wf2^T [n=128][k=128] bf16 hi/lo, 256B rows, XOR-swizzled

// ---------------------------------------------------------------- helpers
__device__ __forceinline__ uint32_t smem_u32(const void* p) {
    uint32_t a;
    asm("{ .reg .u64 t; cvta.to.shared.u64 t, %1; cvt.u32.u64 %0, t; }" : "=r"(a) : "l"(p));
    return a;
}
__device__ __forceinline__ float sspf(float x) {
    float e = __expf(-fabsf(x));
    return fmaxf(x, 0.0f) + __logf(1.0f + e) - 0.6931471805599453f;
}
__device__ __forceinline__ void red_add_v2(float* p, float a, float b) {
    asm volatile("red.global.add.v2.f32 [%0], {%1,%2};"
                 :: "l"(p), "f"(a), "f"(b) : "memory");
}
__device__ __forceinline__ void split_pack(float a, float b, uint32_t& hi, uint32_t& lo) {
    __nv_bfloat16 ah = __float2bfloat16(a), bh = __float2bfloat16(b);
    float ar = a - __bfloat162float(ah);
    float br = b - __bfloat162float(bh);
    __nv_bfloat16 al = __float2bfloat16(ar), bl = __float2bfloat16(br);
    hi = ((uint32_t)__bfloat16_as_ushort(bh) << 16) | (uint32_t)__bfloat16_as_ushort(ah);
    lo = ((uint32_t)__bfloat16_as_ushort(bl) << 16) | (uint32_t)__bfloat16_as_ushort(al);
}
__device__ __forceinline__ void mma16816(float* c, const uint32_t* a, const uint32_t* b) {
    asm volatile("mma.sync.aligned.m16n8k16.row.col.f32.bf16.bf16.f32 "
                 "{%0,%1,%2,%3}, {%4,%5,%6,%7}, {%8,%9}, {%0,%1,%2,%3};"
                 : "+f"(c[0]), "+f"(c[1]), "+f"(c[2]), "+f"(c[3])
                 : "r"(a[0]), "r"(a[1]), "r"(a[2]), "r"(a[3]), "r"(b[0]), "r"(b[1]));
}
__device__ __forceinline__ void ldsm_x4(uint32_t* r, uint32_t addr) {
    asm volatile("ldmatrix.sync.aligned.m8n8.x4.shared.b16 {%0,%1,%2,%3}, [%4];"
                 : "=r"(r[0]), "=r"(r[1]), "=r"(r[2]), "=r"(r[3]) : "r"(addr));
}

#define FMA8(av, b0, b1, ar) do {                                     \
    ar[0] = fmaf(av, b0.x, ar[0]); ar[1] = fmaf(av, b0.y, ar[1]);     \
    ar[2] = fmaf(av, b0.z, ar[2]); ar[3] = fmaf(av, b0.w, ar[3]);     \
    ar[4] = fmaf(av, b1.x, ar[4]); ar[5] = fmaf(av, b1.y, ar[5]);     \
    ar[6] = fmaf(av, b1.z, ar[6]); ar[7] = fmaf(av, b1.w, ar[7]); } while (0)

template<int KDIM, int LDA>
__device__ __forceinline__ void gemm_tile(const float* sA, const float* sB,
                                          int rl, int n0, float acc[8][8]) {
#pragma unroll 1
    for (int k4 = 0; k4 < KDIM; k4 += 4) {
        float4 a[8];
#pragma unroll
        for (int i = 0; i < 8; i++)
            a[i] = *(const float4*)(sA + (rl + i) * LDA + k4);
        float4 b00 = *(const float4*)(sB + (k4 + 0) * F + n0);
        float4 b01 = *(const float4*)(sB + (k4 + 0) * F + n0 + 4);
        float4 b10 = *(const float4*)(sB + (k4 + 1) * F + n0);
        float4 b11 = *(const float4*)(sB + (k4 + 1) * F + n0 + 4);
        float4 b20 = *(const float4*)(sB + (k4 + 2) * F + n0);
        float4 b21 = *(const float4*)(sB + (k4 + 2) * F + n0 + 4);
        float4 b30 = *(const float4*)(sB + (k4 + 3) * F + n0);
        float4 b31 = *(const float4*)(sB + (k4 + 3) * F + n0 + 4);
#pragma unroll
        for (int i = 0; i < 8; i++) {
            FMA8(a[i].x, b00, b01, acc[i]);
            FMA8(a[i].y, b10, b11, acc[i]);
            FMA8(a[i].z, b20, b21, acc[i]);
            FMA8(a[i].w, b30, b31, acc[i]);
        }
    }
}

// ---------------------------------------------------------------- prep: W2 image
__global__ void k_prep(const float* __restrict__ Wf2) {
    int idx = blockIdx.x * blockDim.x + threadIdx.x;
    if (idx < 16384) {                 // Wf2 [k=128][n=128] -> [n][k], swizzled
        int k = idx >> 7, n = idx & 127;
        float w = Wf2[idx];
        __nv_bfloat16 h = __float2bfloat16(w);
        float r = w - __bfloat162float(h);
        uint32_t off = (uint32_t)n * 256u + ((uint32_t)((k >> 3) ^ (n & 7)) << 4) + (uint32_t)(k & 7) * 2u;
        *(__nv_bfloat16*)(g_W2T[0] + off) = h;
        *(__nv_bfloat16*)(g_W2T[1] + off) = __float2bfloat16(r);
    }
}

// ---------------------------------------------------------------- zero acc
__global__ void k_zero(int n4) {
    int i = blockIdx.x * blockDim.x + threadIdx.x;
    if (i < n4) reinterpret_cast<float4*>(g_acc)[i] = make_float4(0.f, 0.f, 0.f, 0.f);
}

// ---------------------------------------------------------------- h = x @ W_in (SIMT fp32)
__global__ __launch_bounds__(NT, 1)
void k_input_proj(const float* __restrict__ x, const float* __restrict__ Win, int N) {
    extern __shared__ float sm[];
    float* sA = sm;
    float* sB = sm + F * F;
    const int tid = threadIdx.x;
    const int r0 = blockIdx.x * F;
    for (int t = tid; t < F * F / 4; t += NT) {
        int row = t >> 5, c4 = (t & 31) << 2;
        float4 v = make_float4(0.f, 0.f, 0.f, 0.f);
        if (r0 + row < N) v = *(const float4*)(x + (size_t)(r0 + row) * F + c4);
        *(float4*)(sA + row * F + c4) = v;
        *(float4*)(sB + row * F + c4) = *(const float4*)(Win + row * F + c4);
    }
    __syncthreads();
    const int tn = tid & 15, tp = tid >> 4;
    const int n0 = tn * 8, rl = tp * 8;
    float acc[8][8];
#pragma unroll
    for (int i = 0; i < 8; i++)
#pragma unroll
        for (int j = 0; j < 8; j++) acc[i][j] = 0.f;
    gemm_tile<F, F>(sA, sB, rl, n0, acc);
#pragma unroll
    for (int i = 0; i < 8; i++) {
        int r = r0 + rl + i;
        if (r < N) {
            *(float4*)(g_h + (size_t)r * F + n0)     = make_float4(acc[i][0], acc[i][1], acc[i][2], acc[i][3]);
            *(float4*)(g_h + (size_t)r * F + n0 + 4) = make_float4(acc[i][4], acc[i][5], acc[i][6], acc[i][7]);
        }
    }
}

// ---------------------------------------------------------------- pair kernel
// SMEM: W2hi 32K | W2lo 32K | A2hi 16K | A2lo 16K | bf1 512 | bf2 512
#define SM_W2HI 0
#define SM_W2LO 32768
#define SM_A2HI 65536
#define SM_A2LO 81920
#define SM_BF1  98304
#define SM_BF2  98816
#define SM_PAIR_TOTAL 99328

__global__ __launch_bounds__(256, 2)
void k_pairs_mma(const float* __restrict__ f_ij, const float* __restrict__ fcut,
                 const int* __restrict__ pairlist, int P, int ntiles,
                 const float* __restrict__ Wf1,
                 const float* __restrict__ bf1, const float* __restrict__ bf2) {
    extern __shared__ char smc[];
    const uint32_t sb = smem_u32(smc);
    const int tid  = threadIdx.x;
    const int wid  = tid >> 5;
    const int lane = tid & 31;
    const int wm   = wid >> 2;          // 0..1  rows 32*wm
    const int wn   = wid & 3;           // 0..3  cols 32*wn
    const int rbase = 32 * wm;
    const int cbase = 32 * wn;
    const int g  = lane >> 2;           // 0..7
    const int t2 = (lane & 3) * 2;      // 0,2,4,6
    const int mi = lane >> 3;           // 0..3 (ldmatrix id)
    const int l8 = lane & 7;

    // ---- stage W2 + biases into SMEM (once) ----
    {
        const uint4* s0 = (const uint4*)g_W2T[0]; uint4* d0 = (uint4*)(smc + SM_W2HI);
        for (int t = tid; t < 2048; t += 256) d0[t] = s0[t];
        const uint4* s1 = (const uint4*)g_W2T[1]; uint4* d1 = (uint4*)(smc + SM_W2LO);
        for (int t = tid; t < 2048; t += 256) d1[t] = s1[t];
        if (tid < 128) {
            ((float*)(smc + SM_BF1))[tid] = bf1[tid];
            ((float*)(smc + SM_BF2))[tid] = bf2[tid];
        }
    }

    // ---- preload W1 B-fragments into registers (once) ----
    // w1hi[ks][ng][4]: {b0,b1} for n8-half0, {b2,b3} for n8-half1
    uint32_t w1hi[2][2][4], w1lo[2][2][4];
#pragma unroll
    for (int ks = 0; ks < 2; ks++)
#pragma unroll
        for (int ng = 0; ng < 2; ng++)
#pragma unroll
            for (int h = 0; h < 2; h++) {
                int n = cbase + 16 * ng + 8 * h + g;
                int k = 16 * ks + t2;
                float b00 = __ldg(Wf1 + (size_t)k * F + n);
                float b01 = __ldg(Wf1 + (size_t)(k + 1) * F + n);
                float b10 = __ldg(Wf1 + (size_t)(k + 8) * F + n);
                float b11 = __ldg(Wf1 + (size_t)(k + 9) * F + n);
                split_pack(b00, b01, w1hi[ks][ng][2 * h],     w1lo[ks][ng][2 * h]);
                split_pack(b10, b11, w1hi[ks][ng][2 * h + 1], w1lo[ks][ng][2 * h + 1]);
            }

    const float* b1s = (const float*)(smc + SM_BF1);
    const float* b2s = (const float*)(smc + SM_BF2);
    __syncthreads();   // W2 image + biases visible

    const int l4 = lane >> 2;
    const int l2 = (lane & 3) * 2;

    for (int tile = blockIdx.x; tile < ntiles; tile += gridDim.x) {
        const int p0 = tile * TP;

        float acc[2][4][4];
#pragma unroll
        for (int a = 0; a < 2; a++)
#pragma unroll
            for (int b = 0; b < 4; b++)
#pragma unroll
                for (int c = 0; c < 4; c++) acc[a][b][c] = 0.f;

        // ---- stage 1: S = f_ij @ W1 (K=32), A-fragments built from gmem ----
#pragma unroll
        for (int ks = 0; ks < 2; ks++) {
            uint32_t ah[2][4], al[2][4];
#pragma unroll
            for (int mt = 0; mt < 2; mt++) {
                int r = p0 + rbase + 16 * mt + g;
                float2 v0 = make_float2(0.f, 0.f), v1 = v0, v2 = v0, v3 = v0;
                if (r < P) {
                    const float* fp = f_ij + (size_t)r * R + 16 * ks + t2;
                    v0 = *(const float2*)fp;
                    v2 = *(const float2*)(fp + 8);
                }
                if (r + 8 < P) {
                    const float* fp = f_ij + (size_t)(r + 8) * R + 16 * ks + t2;
                    v1 = *(const float2*)fp;
                    v3 = *(const float2*)(fp + 8);
                }
                split_pack(v0.x, v0.y, ah[mt][0], al[mt][0]);
                split_pack(v1.x, v1.y, ah[mt][1], al[mt][1]);
                split_pack(v2.x, v2.y, ah[mt][2], al[mt][2]);
                split_pack(v3.x, v3.y, ah[mt][3], al[mt][3]);
            }
#pragma unroll
            for (int ng = 0; ng < 2; ng++)
#pragma unroll
                for (int mt = 0; mt < 2; mt++) {
                    mma16816(acc[mt][2 * ng],     ah[mt], w1hi[ks][ng]);
                    mma16816(acc[mt][2 * ng],     al[mt], w1hi[ks][ng]);
                    mma16816(acc[mt][2 * ng],     ah[mt], w1lo[ks][ng]);
                    mma16816(acc[mt][2 * ng + 1], ah[mt], w1hi[ks][ng] + 2);
                    mma16816(acc[mt][2 * ng + 1], al[mt], w1hi[ks][ng] + 2);
                    mma16816(acc[mt][2 * ng + 1], ah[mt], w1lo[ks][ng] + 2);
                }
        }

        __syncthreads();   // previous tile's stage-2 reads of A2 done

        // ---- ssp(S + bf1) -> split -> A2 smem (swizzled), reset acc ----
#pragma unroll
        for (int mt = 0; mt < 2; mt++)
#pragma unroll
            for (int nt = 0; nt < 4; nt++) {
                int c = cbase + 8 * nt + l2;
#pragma unroll
                for (int half = 0; half < 2; half++) {
                    int r = rbase + 16 * mt + l4 + 8 * half;
                    float e0 = sspf(acc[mt][nt][2 * half]     + b1s[c]);
                    float e1 = sspf(acc[mt][nt][2 * half + 1] + b1s[c + 1]);
                    uint32_t hi, lo;
                    split_pack(e0, e1, hi, lo);
                    uint32_t off = (uint32_t)r * 256u + ((uint32_t)((c >> 3) ^ (r & 7)) << 4) + (uint32_t)(c & 7) * 2u;
                    *(uint32_t*)(smc + SM_A2HI + off) = hi;
                    *(uint32_t*)(smc + SM_A2LO + off) = lo;
                }
            }
#pragma unroll
        for (int a = 0; a < 2; a++)
#pragma unroll
            for (int b = 0; b < 4; b++)
#pragma unroll
                for (int c = 0; c < 4; c++) acc[a][b][c] = 0.f;

        __syncthreads();   // A2 visible

        // ---- stage 2: W_ij = S @ W2 (K=128) ----
#pragma unroll 1
        for (int ks = 0; ks < 8; ks++) {
            const int k0 = ks * 16;
            uint32_t ah[2][4], al[2][4];
#pragma unroll
            for (int mt = 0; mt < 2; mt++) {
                int r  = rbase + 16 * mt + (mi & 1) * 8 + l8;
                int kb = k0 + (mi >> 1) * 8;
                uint32_t off = (uint32_t)r * 256u + ((uint32_t)((kb >> 3) ^ (r & 7)) << 4);
                ldsm_x4(ah[mt], sb + SM_A2HI + off);
                ldsm_x4(al[mt], sb + SM_A2LO + off);
            }
#pragma unroll
            for (int ng = 0; ng < 2; ng++) {
                int n  = cbase + 16 * ng + (mi >> 1) * 8 + l8;
                int kb = k0 + (mi & 1) * 8;
                uint32_t off = (uint32_t)n * 256u + ((uint32_t)((kb >> 3) ^ (n & 7)) << 4);
                uint32_t bh[4], bl[4];
                ldsm_x4(bh, sb + SM_W2HI + off);
                ldsm_x4(bl, sb + SM_W2LO + off);
#pragma unroll
                for (int mt = 0; mt < 2; mt++) {
                    mma16816(acc[mt][2 * ng],     ah[mt], bh);
                    mma16816(acc[mt][2 * ng],     al[mt], bh);
                    mma16816(acc[mt][2 * ng],     ah[mt], bl);
                    mma16816(acc[mt][2 * ng + 1], ah[mt], bh + 2);
                    mma16816(acc[mt][2 * ng + 1], al[mt], bh + 2);
                    mma16816(acc[mt][2 * ng + 1], ah[mt], bl + 2);
                }
            }
        }

        // ---- epilogue: (W_ij + bf2) * cut * h[idx_j] -> red_add g_acc[idx_i] ----
#pragma unroll
        for (int mt = 0; mt < 2; mt++)
#pragma unroll
            for (int half = 0; half < 2; half++) {
                int rl = rbase + 16 * mt + l4 + 8 * half;
                int p  = p0 + rl;
                if (p < P) {
                    float cu = __ldg(fcut + p);
                    int ai = __ldg(pairlist + p);
                    int aj = __ldg(pairlist + (size_t)P + p);
                    const float* hrow = g_h + (size_t)aj * F;
                    float* arow = g_acc + (size_t)ai * F;
#pragma unroll
                    for (int nt = 0; nt < 4; nt++) {
                        int c = cbase + 8 * nt + l2;
                        float2 hv = *(const float2*)(hrow + c);
                        float vx = (acc[mt][nt][2 * half]     + b2s[c])     * cu * hv.x;
                        float vy = (acc[mt][nt][2 * half + 1] + b2s[c + 1]) * cu * hv.y;
                        red_add_v2(arow + c, vx, vy);
                    }
                }
            }
    }
}

// ---------------------------------------------------------------- out = ssp(acc@Wo1+bo1)@Wo2 + bo2 (SIMT fp32)
__global__ __launch_bounds__(NT, 1)
void k_output(const float* __restrict__ Wo1, const float* __restrict__ bo1,
              const float* __restrict__ Wo2, const float* __restrict__ bo2,
              float* __restrict__ out, int N) {
    extern __shared__ float sm[];
    float* sA = sm;
    float* sW = sA + F * F;
    float* sT = sW + F * F;
    float* sb = sT + F * F;
    const int tid = threadIdx.x;
    const int r0 = blockIdx.x * F;
    for (int t = tid; t < F * F / 4; t += NT) {
        int row = t >> 5, c4 = (t & 31) << 2;
        float4 v = make_float4(0.f, 0.f, 0.f, 0.f);
        if (r0 + row < N) v = *(const float4*)(g_acc + (size_t)(r0 + row) * F + c4);
        *(float4*)(sA + row * F + c4) = v;
        *(float4*)(sW + row * F + c4) = *(const float4*)(Wo1 + row * F + c4);
    }
    if (tid < F) { sb[tid] = bo1[tid]; sb[F + tid] = bo2[tid]; }
    __syncthreads();
    const int tn = tid & 15, tp = tid >> 4;
    const int n0 = tn * 8, rl = tp * 8;
    float acc[8][8];
#pragma unroll
    for (int i = 0; i < 8; i++)
#pragma unroll
        for (int j = 0; j < 8; j++) acc[i][j] = 0.f;
    gemm_tile<F, F>(sA, sW, rl, n0, acc);
    float4 bb0 = *(const float4*)(sb + n0);
    float4 bb1 = *(const float4*)(sb + n0 + 4);
#pragma unroll
    for (int i = 0; i < 8; i++) {
        float4 v0, v1;
        v0.x = sspf(acc[i][0] + bb0.x); v0.y = sspf(acc[i][1] + bb0.y);
        v0.z = sspf(acc[i][2] + bb0.z); v0.w = sspf(acc[i][3] + bb0.w);
        v1.x = sspf(acc[i][4] + bb1.x); v1.y = sspf(acc[i][5] + bb1.y);
        v1.z = sspf(acc[i][6] + bb1.z); v1.w = sspf(acc[i][7] + bb1.w);
        *(float4*)(sT + (rl + i) * F + n0)     = v0;
        *(float4*)(sT + (rl + i) * F + n0 + 4) = v1;
#pragma unroll
        for (int j = 0; j < 8; j++) acc[i][j] = 0.f;
    }
    __syncthreads();
    for (int t = tid; t < F * F / 4; t += NT) {
        int row = t >> 5, c4 = (t & 31) << 2;
        *(float4*)(sW + row * F + c4) = *(const float4*)(Wo2 + row * F + c4);
    }
    __syncthreads();
    gemm_tile<F, F>(sT, sW, rl, n0, acc);
    float4 d0 = *(const float4*)(sb + F + n0);
    float4 d1 = *(const float4*)(sb + F + n0 + 4);
#pragma unroll
    for (int i = 0; i < 8; i++) {
        int r = r0 + rl + i;
        if (r < N) {
            *(float4*)(out + (size_t)r * F + n0) =
                make_float4(acc[i][0] + d0.x, acc[i][1] + d0.y, acc[i][2] + d0.z, acc[i][3] + d0.w);
            *(float4*)(out + (size_t)r * F + n0 + 4) =
                make_float4(acc[i][4] + d1.x, acc[i][5] + d1.y, acc[i][6] + d1.z, acc[i][7] + d1.w);
        }
    }
}

// ----------------------------------------------------------------- launcher
extern "C" void kernel_launch(void* const* d_in, const int* in_sizes, int n_in,
                              void* d_out, int out_size) {
    const float* x    = (const float*)d_in[0];
    const int*   pl   = (const int*)  d_in[1];
    const float* f_ij = (const float*)d_in[2];
    const float* fcut = (const float*)d_in[3];
    const float* Win  = (const float*)d_in[4];
    const float* Wf1  = (const float*)d_in[5];
    const float* bf1  = (const float*)d_in[6];
    const float* Wf2  = (const float*)d_in[7];
    const float* bf2  = (const float*)d_in[8];
    const float* Wo1  = (const float*)d_in[9];
    const float* bo1  = (const float*)d_in[10];
    const float* Wo2  = (const float*)d_in[11];
    const float* bo2  = (const float*)d_in[12];
    float* out = (float*)d_out;

    const int N = in_sizes[0] / F;
    const int P = in_sizes[1] / 2;
    const int ntiles = (P + TP - 1) / TP;

    const int smem_proj = 2 * F * F * 4;
    const int smem_out  = 3 * F * F * 4 + 2 * F * 4;

    cudaFuncSetAttribute(k_input_proj, cudaFuncAttributeMaxDynamicSharedMemorySize, smem_proj);
    cudaFuncSetAttribute(k_pairs_mma,  cudaFuncAttributeMaxDynamicSharedMemorySize, SM_PAIR_TOTAL);
    cudaFuncSetAttribute(k_output,     cudaFuncAttributeMaxDynamicSharedMemorySize, smem_out);

    const int n4 = N * F / 4;
    k_prep<<<64, 256>>>(Wf2);
    k_zero<<<(n4 + 255) / 256, 256>>>(n4);
    k_input_proj<<<(N + F - 1) / F, NT, smem_proj>>>(x, Win, N);
    int grid = ntiles < 296 ? ntiles : 296;
    k_pairs_mma<<<grid, 256, SM_PAIR_TOTAL>>>(f_ij, fcut, pl, P, ntiles, Wf1, bf1, bf2);
    k_output<<<(N + F - 1) / F, NT, smem_out>>>(Wo1, bo1, Wo2, bo2, out, N);
}